// round 11
// baseline (speedup 1.0000x reference)
#include <cuda_runtime.h>

#define B_    4
#define NIN   512
#define NOUT  1024
#define C_    64
#define LOG2E 1.4426950408889634f

#define BLOCKS_TOTAL   128     // 32 per batch
#define OUT_PER_BLOCK  32      // 4 outputs per warp

__device__ __forceinline__ float ex2f(float a) {
    float r;
    asm("ex2.approx.ftz.f32 %0, %1;" : "=f"(r) : "f"(a));
    return r;
}

// ---------------------------------------------------------------------------
// Single fused kernel. 128 blocks x 256 threads, ONE __syncthreads.
// Block bk: batch b = bk/32, outputs [bk*32, bk*32+32).
// Phase 1: yw[b,0..511] via 8 threads/row; two half-passes of 8 rows with all
//          16 LDG.128 front-batched per half (max MLP before first FMA).
// Phase 2: each warp owns 4 outputs; lane holds 16 (x,yw) pairs in regs,
//          64 EX2 per lane (4 independent chains), butterfly, float4 store.
// ---------------------------------------------------------------------------
__global__ void __launch_bounds__(256)
fused_kernel(const float* __restrict__ x,
             const float* __restrict__ y,
             const float* __restrict__ t,
             const float* __restrict__ sigma,
             const float* __restrict__ w,
             const float* __restrict__ bias,
             float* __restrict__ out) {
    __shared__ float4 sx4[NIN / 4];        // 128 float4: x row
    __shared__ float4 syw4[NIN / 4];       // 128 float4: yw row
    __shared__ float  skd[C_];             // per-channel kd (fallback path)
    __shared__ int    s_uniform;
    __shared__ float  s_kd0, s_bias;

    const int tid  = threadIdx.x;
    const int o0   = blockIdx.x * OUT_PER_BLOCK;
    const int b    = o0 >> 10;             // NOUT = 1024

    const int warp = tid >> 5;
    const int lane = tid & 31;
    const int oA   = o0 + warp * 4;

    const int sub = tid & 7;               // channel-octet owner
    const int rw0 = tid >> 3;              // 0..31

    // ---- issue w octet loads first (needed by phase-1 FMAs) ----
    float4 wv0 = __ldg(&((const float4*)w)[sub * 2 + 0]);
    float4 wv1 = __ldg(&((const float4*)w)[sub * 2 + 1]);

    // ---- pre-barrier scalar loads (independent of smem) ----
    float t0 = __ldg(&t[oA + 0]);
    float t1 = __ldg(&t[oA + 1]);
    float t2 = __ldg(&t[oA + 2]);
    float t3 = __ldg(&t[oA + 3]);

    // x staging rides along (tids 0..127)
    if (tid < NIN / 4)
        sx4[tid] = __ldg(&((const float4*)(x + b * NIN))[tid]);

    // per-channel kd for fallback (tids 128..191)
    if (tid >= 128 && tid < 128 + C_) {
        int c = tid - 128;
        skd[c] = -0.5f * LOG2E * expf(-2.0f * sigma[c]);
    }
    // uniformity flag + scalars (warp 6 exactly)
    if (tid >= 192 && tid < 224) {
        int l = tid - 192;
        float s0f = sigma[l];
        unsigned b0 = __float_as_uint(s0f);
        unsigned b1 = __float_as_uint(sigma[l + 32]);
        unsigned ref = __shfl_sync(0xffffffffu, b0, 0);
        unsigned ok  = __ballot_sync(0xffffffffu, b0 == ref && b1 == ref);
        if (l == 0) {
            s_uniform = (ok == 0xffffffffu);
            s_kd0  = -0.5f * LOG2E * expf(-2.0f * s0f);
            s_bias = bias[0];
        }
    }

    // ---- phase 1: yw[row] = dot(y[b,row,:], w); 8 threads per row ----
    // Two half-passes; each front-batches all 16 LDG.128 before FMAs.
    {
        float* syw = (float*)syw4;
        const float* ybase = y + ((size_t)b * NIN) * C_ + sub * 8;
        #pragma unroll
        for (int half = 0; half < 2; half++) {
            float4 r0[8], r1[8];
            #pragma unroll
            for (int p = 0; p < 8; p++) {
                int row = (half * 8 + p) * 32 + rw0;
                const float4* yp = (const float4*)(ybase + (size_t)row * C_);
                r0[p] = __ldg(&yp[0]);
                r1[p] = __ldg(&yp[1]);
            }
            #pragma unroll
            for (int p = 0; p < 8; p++) {
                int row = (half * 8 + p) * 32 + rw0;
                float acc = r0[p].x * wv0.x + r0[p].y * wv0.y
                          + r0[p].z * wv0.z + r0[p].w * wv0.w
                          + r1[p].x * wv1.x + r1[p].y * wv1.y
                          + r1[p].z * wv1.z + r1[p].w * wv1.w;
                acc += __shfl_down_sync(0xffffffffu, acc, 4, 8);
                acc += __shfl_down_sync(0xffffffffu, acc, 2, 8);
                acc += __shfl_down_sync(0xffffffffu, acc, 1, 8);
                if (sub == 0) syw[row] = acc;
            }
        }
    }
    __syncthreads();

    // ---- phase 2: 4 outputs per warp ----
    if (s_uniform) {
        const float kd = s_kd0;
        float a0 = 0.f, a1 = 0.f, a2 = 0.f, a3 = 0.f;
        #pragma unroll
        for (int q = 0; q < 4; q++) {
            float4 xv = sx4 [lane * 4 + q];
            float4 wv = syw4[lane * 4 + q];
            float d;
            d = xv.x - t0; a0 += wv.x * ex2f(kd * d * d);
            d = xv.x - t1; a1 += wv.x * ex2f(kd * d * d);
            d = xv.x - t2; a2 += wv.x * ex2f(kd * d * d);
            d = xv.x - t3; a3 += wv.x * ex2f(kd * d * d);
            d = xv.y - t0; a0 += wv.y * ex2f(kd * d * d);
            d = xv.y - t1; a1 += wv.y * ex2f(kd * d * d);
            d = xv.y - t2; a2 += wv.y * ex2f(kd * d * d);
            d = xv.y - t3; a3 += wv.y * ex2f(kd * d * d);
            d = xv.z - t0; a0 += wv.z * ex2f(kd * d * d);
            d = xv.z - t1; a1 += wv.z * ex2f(kd * d * d);
            d = xv.z - t2; a2 += wv.z * ex2f(kd * d * d);
            d = xv.z - t3; a3 += wv.z * ex2f(kd * d * d);
            d = xv.w - t0; a0 += wv.w * ex2f(kd * d * d);
            d = xv.w - t1; a1 += wv.w * ex2f(kd * d * d);
            d = xv.w - t2; a2 += wv.w * ex2f(kd * d * d);
            d = xv.w - t3; a3 += wv.w * ex2f(kd * d * d);
        }
        #pragma unroll
        for (int off = 16; off; off >>= 1) {
            a0 += __shfl_xor_sync(0xffffffffu, a0, off);
            a1 += __shfl_xor_sync(0xffffffffu, a1, off);
            a2 += __shfl_xor_sync(0xffffffffu, a2, off);
            a3 += __shfl_xor_sync(0xffffffffu, a3, off);
        }
        if (lane == 0) {
            float bb = s_bias;
            ((float4*)(out + oA))[0] =
                make_float4(a0 + bb, a1 + bb, a2 + bb, a3 + bb);
        }
    } else {
        // General per-channel-scale fallback: lanes own 2 channels each.
        const float* sx = (const float*)sx4;
        const float k0 = skd[lane], k1 = skd[lane + 32];
        const float w0 = __ldg(&w[lane]), w1 = __ldg(&w[lane + 32]);
        float tm4[4] = {t0, t1, t2, t3};
        #pragma unroll 1
        for (int j = 0; j < 4; j++) {
            const float tm = tm4[j];
            float p0 = 0.0f, p1 = 0.0f;
            for (int n = 0; n < NIN; n++) {
                float d  = sx[n] - tm;
                float d2 = d * d;
                const float* yr = y + ((size_t)(b * NIN + n)) * C_;
                p0 += __ldg(&yr[lane])      * ex2f(k0 * d2);
                p1 += __ldg(&yr[lane + 32]) * ex2f(k1 * d2);
            }
            float acc2 = p0 * w0 + p1 * w1;
            #pragma unroll
            for (int off = 16; off; off >>= 1)
                acc2 += __shfl_xor_sync(0xffffffffu, acc2, off);
            if (lane == 0) out[oA + j] = acc2 + s_bias;
        }
    }
}

// ---------------------------------------------------------------------------
// Input order (setup_inputs): x, y, t, sigma, w, b
// ---------------------------------------------------------------------------
extern "C" void kernel_launch(void* const* d_in, const int* in_sizes, int n_in,
                              void* d_out, int out_size) {
    const float* x     = (const float*)d_in[0];
    const float* y     = (const float*)d_in[1];
    const float* t     = (const float*)d_in[2];
    const float* sigma = (const float*)d_in[3];
    const float* w     = (const float*)d_in[4];
    const float* bias  = (const float*)d_in[5];
    float* out = (float*)d_out;

    fused_kernel<<<BLOCKS_TOTAL, 256>>>(x, y, t, sigma, w, bias, out);
}

// round 12
// speedup vs baseline: 1.0294x; 1.0294x over previous
#include <cuda_runtime.h>

#define B_    4
#define NIN   512
#define NOUT  1024
#define C_    64
#define LOG2E 1.4426950408889634f

#define BLOCKS_TOTAL   128     // 32 per batch
#define OUT_PER_BLOCK  32      // 4 outputs per warp

__device__ __forceinline__ float ex2f(float a) {
    float r;
    asm("ex2.approx.ftz.f32 %0, %1;" : "=f"(r) : "f"(a));
    return r;
}

// ---------------------------------------------------------------------------
// Single fused kernel. 128 blocks x 256 threads, ONE __syncthreads.
// Block bk: batch b = bk/32, outputs [bk*32, bk*32+32).
// Phase 1 (no prior barrier): yw[b,0..511] via 8 threads/row, w octets in
//          registers (__ldg broadcast); x staged concurrently by tids 0-127.
// Phase 2: each warp owns 4 outputs; lane holds 16 (x,yw) pairs in regs,
//          64 EX2 per lane (4 independent chains), butterfly, float4 store.
// Best-measured configuration (8.704us): unroll-8 phase 1, 47 regs.
// ---------------------------------------------------------------------------
__global__ void __launch_bounds__(256)
fused_kernel(const float* __restrict__ x,
             const float* __restrict__ y,
             const float* __restrict__ t,
             const float* __restrict__ sigma,
             const float* __restrict__ w,
             const float* __restrict__ bias,
             float* __restrict__ out) {
    __shared__ float4 sx4[NIN / 4];        // 128 float4: x row
    __shared__ float4 syw4[NIN / 4];       // 128 float4: yw row
    __shared__ float  skd[C_];             // per-channel kd (fallback path)
    __shared__ int    s_uniform;
    __shared__ float  s_kd0, s_bias;

    const int tid  = threadIdx.x;
    const int o0   = blockIdx.x * OUT_PER_BLOCK;
    const int b    = o0 >> 10;             // NOUT = 1024

    const int warp = tid >> 5;
    const int lane = tid & 31;
    const int oA   = o0 + warp * 4;

    // ---- pre-barrier scalar loads (independent of smem) ----
    float t0 = __ldg(&t[oA + 0]);
    float t1 = __ldg(&t[oA + 1]);
    float t2 = __ldg(&t[oA + 2]);
    float t3 = __ldg(&t[oA + 3]);

    // x staging rides along (tids 0..127)
    if (tid < NIN / 4)
        sx4[tid] = __ldg(&((const float4*)(x + b * NIN))[tid]);

    // per-channel kd for fallback (tids 128..191)
    if (tid >= 128 && tid < 128 + C_) {
        int c = tid - 128;
        skd[c] = -0.5f * LOG2E * expf(-2.0f * sigma[c]);
    }
    // uniformity flag + scalars (warp 6 exactly)
    if (tid >= 192 && tid < 224) {
        int l = tid - 192;
        float s0f = sigma[l];
        unsigned b0 = __float_as_uint(s0f);
        unsigned b1 = __float_as_uint(sigma[l + 32]);
        unsigned ref = __shfl_sync(0xffffffffu, b0, 0);
        unsigned ok  = __ballot_sync(0xffffffffu, b0 == ref && b1 == ref);
        if (l == 0) {
            s_uniform = (ok == 0xffffffffu);
            s_kd0  = -0.5f * LOG2E * expf(-2.0f * s0f);
            s_bias = bias[0];
        }
    }

    // ---- phase 1: yw[row] = dot(y[b,row,:], w); 8 threads per row ----
    {
        const int sub = tid & 7;           // channel-octet owner
        const int rw0 = tid >> 3;          // 0..31
        float4 wv0 = __ldg(&((const float4*)w)[sub * 2 + 0]);
        float4 wv1 = __ldg(&((const float4*)w)[sub * 2 + 1]);
        float* syw = (float*)syw4;
        #pragma unroll 8
        for (int pass = 0; pass < 16; pass++) {
            int row = pass * 32 + rw0;
            const float4* yp = (const float4*)(y + ((size_t)(b * NIN + row)) * C_ + sub * 8);
            float4 y0 = __ldg(&yp[0]);
            float4 y1 = __ldg(&yp[1]);
            float acc = y0.x * wv0.x + y0.y * wv0.y + y0.z * wv0.z + y0.w * wv0.w
                      + y1.x * wv1.x + y1.y * wv1.y + y1.z * wv1.z + y1.w * wv1.w;
            acc += __shfl_down_sync(0xffffffffu, acc, 4, 8);
            acc += __shfl_down_sync(0xffffffffu, acc, 2, 8);
            acc += __shfl_down_sync(0xffffffffu, acc, 1, 8);
            if (sub == 0) syw[row] = acc;
        }
    }
    __syncthreads();

    // ---- phase 2: 4 outputs per warp ----
    if (s_uniform) {
        const float kd = s_kd0;
        float a0 = 0.f, a1 = 0.f, a2 = 0.f, a3 = 0.f;
        #pragma unroll
        for (int q = 0; q < 4; q++) {
            float4 xv = sx4 [lane * 4 + q];
            float4 wv = syw4[lane * 4 + q];
            float d;
            d = xv.x - t0; a0 += wv.x * ex2f(kd * d * d);
            d = xv.x - t1; a1 += wv.x * ex2f(kd * d * d);
            d = xv.x - t2; a2 += wv.x * ex2f(kd * d * d);
            d = xv.x - t3; a3 += wv.x * ex2f(kd * d * d);
            d = xv.y - t0; a0 += wv.y * ex2f(kd * d * d);
            d = xv.y - t1; a1 += wv.y * ex2f(kd * d * d);
            d = xv.y - t2; a2 += wv.y * ex2f(kd * d * d);
            d = xv.y - t3; a3 += wv.y * ex2f(kd * d * d);
            d = xv.z - t0; a0 += wv.z * ex2f(kd * d * d);
            d = xv.z - t1; a1 += wv.z * ex2f(kd * d * d);
            d = xv.z - t2; a2 += wv.z * ex2f(kd * d * d);
            d = xv.z - t3; a3 += wv.z * ex2f(kd * d * d);
            d = xv.w - t0; a0 += wv.w * ex2f(kd * d * d);
            d = xv.w - t1; a1 += wv.w * ex2f(kd * d * d);
            d = xv.w - t2; a2 += wv.w * ex2f(kd * d * d);
            d = xv.w - t3; a3 += wv.w * ex2f(kd * d * d);
        }
        #pragma unroll
        for (int off = 16; off; off >>= 1) {
            a0 += __shfl_xor_sync(0xffffffffu, a0, off);
            a1 += __shfl_xor_sync(0xffffffffu, a1, off);
            a2 += __shfl_xor_sync(0xffffffffu, a2, off);
            a3 += __shfl_xor_sync(0xffffffffu, a3, off);
        }
        if (lane == 0) {
            float bb = s_bias;
            ((float4*)(out + oA))[0] =
                make_float4(a0 + bb, a1 + bb, a2 + bb, a3 + bb);
        }
    } else {
        // General per-channel-scale fallback: lanes own 2 channels each.
        const float* sx = (const float*)sx4;
        const float k0 = skd[lane], k1 = skd[lane + 32];
        const float w0 = __ldg(&w[lane]), w1 = __ldg(&w[lane + 32]);
        float tm4[4] = {t0, t1, t2, t3};
        #pragma unroll 1
        for (int j = 0; j < 4; j++) {
            const float tm = tm4[j];
            float p0 = 0.0f, p1 = 0.0f;
            for (int n = 0; n < NIN; n++) {
                float d  = sx[n] - tm;
                float d2 = d * d;
                const float* yr = y + ((size_t)(b * NIN + n)) * C_;
                p0 += __ldg(&yr[lane])      * ex2f(k0 * d2);
                p1 += __ldg(&yr[lane + 32]) * ex2f(k1 * d2);
            }
            float acc2 = p0 * w0 + p1 * w1;
            #pragma unroll
            for (int off = 16; off; off >>= 1)
                acc2 += __shfl_xor_sync(0xffffffffu, acc2, off);
            if (lane == 0) out[oA + j] = acc2 + s_bias;
        }
    }
}

// ---------------------------------------------------------------------------
// Input order (setup_inputs): x, y, t, sigma, w, b
// ---------------------------------------------------------------------------
extern "C" void kernel_launch(void* const* d_in, const int* in_sizes, int n_in,
                              void* d_out, int out_size) {
    const float* x     = (const float*)d_in[0];
    const float* y     = (const float*)d_in[1];
    const float* t     = (const float*)d_in[2];
    const float* sigma = (const float*)d_in[3];
    const float* w     = (const float*)d_in[4];
    const float* bias  = (const float*)d_in[5];
    float* out = (float*)d_out;

    fused_kernel<<<BLOCKS_TOTAL, 256>>>(x, y, t, sigma, w, bias, out);
}